// round 13
// baseline (speedup 1.0000x reference)
#include <cuda_runtime.h>
#include <cstdint>

// DetectionLayer: x (16, 255, 76, 76) f32 -> out (16, 17328, 85) f32
// Block = (b, a, 2 gy rows). One 608B TMA bulk load per channel (85 ops),
// conflict-free smem transform, one 51680B TMA bulk store. Overlap across
// 2 CTAs/SM. Minimizes TMA engine op count (engine is op-rate limited).

#define NG     76
#define NGG    (NG * NG)      // 5776
#define NA     3
#define NCH    85
#define NROWS  2              // gy rows per block
#define SPW    (NROWS * NG)   // 152 spatial positions per block
#define SEG_B  (SPW * 4)      // 608 bytes per channel segment
#define TILE_F (SPW * NCH)    // 12920 floats (both in and out bufs)
#define TILE_B (TILE_F * 4)   // 51680 bytes
#define NITEM  (21 * SPW)     // 3192 quad items
#define NTHR   512

// dynamic smem: in @ 0 (channel-major: c*152 + s), out @ TILE_F (s*85 + c)
#define SMEM_B (2 * TILE_B)   // 103360 bytes

__device__ __forceinline__ float tanh_half(float v) {
    float t;
    asm("tanh.approx.f32 %0, %1;" : "=f"(t) : "f"(v * 0.5f));
    return t;  // tanh(v/2); sigmoid(v) = fmaf(t, 0.5f, 0.5f)
}

__global__ __launch_bounds__(NTHR)
void detection_layer_kernel(const float* __restrict__ x, float* __restrict__ out) {
    extern __shared__ __align__(16) float smem[];
    __shared__ __align__(8) uint64_t mbar;

    const int tid = threadIdx.x;
    const int gy0 = blockIdx.x * NROWS;  // 0,2,..,74
    const int a   = blockIdx.y;          // 0..2
    const int b   = blockIdx.z;          // 0..15

    const float aw = (a == 0) ? 10.0f : (a == 1 ? 16.0f : 33.0f);
    const float ah = (a == 0) ? 13.0f : (a == 1 ? 30.0f : 23.0f);

    // global input base for (b, a*85, gy0, 0) in bytes
    const char* srcb = (const char*)x +
        ((size_t)(b * (NA * NCH) + a * NCH) * NGG + (size_t)gy0 * NG) * 4;
    float* dst = out + ((size_t)b * (NA * NGG) + a * NGG + (size_t)gy0 * NG) * NCH;

    uint32_t sbase;
    asm("{ .reg .u64 t; cvta.to.shared.u64 t, %1; cvt.u32.u64 %0, t; }"
        : "=r"(sbase) : "l"(smem));
    uint32_t mbase;
    asm("{ .reg .u64 t; cvta.to.shared.u64 t, %1; cvt.u32.u64 %0, t; }"
        : "=r"(mbase) : "l"(&mbar));

    // init mbarrier + arm expected bytes (whole input tile)
    if (tid == 0) {
        asm volatile("mbarrier.init.shared.b64 [%0], 1;" :: "r"(mbase) : "memory");
        asm volatile("fence.proxy.async.shared::cta;" ::: "memory");
        asm volatile("mbarrier.arrive.expect_tx.shared.b64 _, [%0], %1;"
                     :: "r"(mbase), "r"((uint32_t)TILE_B) : "memory");
    }
    __syncthreads();

    // one 608B bulk load per channel (covers both gy rows)
    if (tid < NCH) {
        asm volatile(
            "cp.async.bulk.shared::cluster.global.mbarrier::complete_tx::bytes "
            "[%0], [%1], %2, [%3];"
            :: "r"(sbase + (uint32_t)(tid * SEG_B)),
               "l"((uint64_t)(srcb + (size_t)tid * (NGG * 4))),
               "r"((uint32_t)SEG_B), "r"(mbase)
            : "memory");
    }

    // wait for the whole input tile
    {
        uint32_t done;
        asm volatile(
            "{ .reg .pred p; mbarrier.try_wait.parity.shared.b64 p, [%1], 0; "
            "selp.b32 %0, 1, 0, p; }"
            : "=r"(done) : "r"(mbase) : "memory");
        while (!done) {
            asm volatile(
                "{ .reg .pred p; mbarrier.try_wait.parity.shared.b64 p, [%1], 0, 0x989680; "
                "selp.b32 %0, 1, 0, p; }"
                : "=r"(done) : "r"(mbase) : "memory");
        }
    }
    __syncthreads();

    // ---- compute: in (c*152+s) -> out (s*85+c), conflict-free ----
    {
        const float* __restrict__ ib = smem;
        float* __restrict__ ob = smem + TILE_F;

        int cg = tid / SPW;          // one div, once
        int s  = tid - cg * SPW;
        #pragma unroll 1
        for (int i = tid; i < NITEM; i += NTHR) {
            const float* p = ib + (cg << 2) * SPW + s;
            const float v0 = p[0];
            const float v1 = p[SPW];
            const float v2 = p[2 * SPW];
            const float v3 = p[3 * SPW];

            float o0, o1, o2, o3;
            if (cg == 0) {
                const int hi = (s >= NG);
                const float gx = (float)(s - (hi ? NG : 0));
                const float gy = (float)(gy0 + hi);
                o0 = fmaf(tanh_half(v0), 4.0f, fmaf(gx, 8.0f, 4.0f));
                o1 = fmaf(tanh_half(v1), 4.0f, fmaf(gy, 8.0f, 4.0f));
                o2 = __expf(v2) * aw;
                o3 = __expf(v3) * ah;
            } else {
                o0 = fmaf(tanh_half(v0), 0.5f, 0.5f);
                o1 = fmaf(tanh_half(v1), 0.5f, 0.5f);
                o2 = fmaf(tanh_half(v2), 0.5f, 0.5f);
                o3 = fmaf(tanh_half(v3), 0.5f, 0.5f);
            }
            float* t = ob + s * NCH + (cg << 2);
            t[0] = o0; t[1] = o1; t[2] = o2; t[3] = o3;

            // i += 512 => cg += 3, s += 56  (512 = 3*152 + 56)
            cg += 3; s += 56;
            if (s >= SPW) { s -= SPW; ++cg; }
        }
        // tail channel 84 (152 elements, conflict-free stride-85 STS)
        if (tid < SPW) {
            ob[tid * NCH + 84] =
                fmaf(tanh_half(ib[84 * SPW + tid]), 0.5f, 0.5f);
        }
    }
    __syncthreads();

    // ---- single TMA bulk store (51680 B, both rows) ----
    if (tid == 0) {
        asm volatile("fence.proxy.async.shared::cta;" ::: "memory");
        asm volatile(
            "cp.async.bulk.global.shared::cta.bulk_group [%0], [%1], %2;"
            :: "l"(dst), "r"(sbase + (uint32_t)TILE_B), "r"((uint32_t)TILE_B)
            : "memory");
        asm volatile("cp.async.bulk.commit_group;" ::: "memory");
        // keep CTA alive until the engine has read the tile
        asm volatile("cp.async.bulk.wait_group.read 0;" ::: "memory");
    }
}

extern "C" void kernel_launch(void* const* d_in, const int* in_sizes, int n_in,
                              void* d_out, int out_size) {
    const float* x = (const float*)d_in[0];
    float* out = (float*)d_out;

    static bool attr_set = false;
    if (!attr_set) {
        cudaFuncSetAttribute(detection_layer_kernel,
                             cudaFuncAttributeMaxDynamicSharedMemorySize,
                             SMEM_B);
        attr_set = true;
    }

    dim3 grid(NG / NROWS, NA, 16);
    detection_layer_kernel<<<grid, NTHR, SMEM_B>>>(x, out);
}

// round 16
// speedup vs baseline: 1.1963x; 1.1963x over previous
#include <cuda_runtime.h>
#include <cuda.h>
#include <cstdint>

// DetectionLayer: x (16, 255, 76, 76) f32 -> out (16, 17328, 85) f32
// R10 pipeline + single tensor-TMA load per row:
//   1 x cp.async.bulk.tensor.3d per gy row (box 76 x 85) -> channel-major smem
//   warps: conflict-free smem->smem transform (sigmoid/exp/affine)
//   1 x cp.async.bulk s2g store (25840B) per row, bulk_group
// Double-buffered over 4 gy rows per block, 512 threads, 2 CTAs/SM.
// All smem buffers padded to 128B alignment (TMA tensor dst requirement).

#define NG     76
#define NGG    (NG * NG)      // 5776
#define NA     3
#define NCH    85
#define NROWS  4              // gy rows per block
#define ROW_F  (NG * NCH)     // 6460 floats
#define ROW_B  (ROW_F * 4)    // 25840 bytes
#define BUF_F  6464           // padded buffer size: 25856 B (mult of 128)
#define NITEM  (21 * NG)      // 1596 quad items per row
#define NTHR   512

// dynamic smem layout (floats), each buffer 128B-aligned:
//   in[0] @ 0 , in[1] @ BUF_F       (channel-major: c*76 + s)
//   out[0] @ 2*BUF_F, out[1] @ 3*BUF_F  (final layout: s*85 + c)
#define IN_OFF(buf)  ((buf) * BUF_F)
#define OUT_OFF(buf) ((2 + (buf)) * BUF_F)
#define SMEM_B (4 * BUF_F * 4)   // 103424 bytes

__device__ __forceinline__ float tanh_half(float v) {
    float t;
    asm("tanh.approx.f32 %0, %1;" : "=f"(t) : "f"(v * 0.5f));
    return t;  // tanh(v/2); sigmoid(v) = fmaf(t, 0.5f, 0.5f)
}

__global__ __launch_bounds__(NTHR)
void detection_layer_kernel(const __grid_constant__ CUtensorMap tmap,
                            float* __restrict__ out) {
    extern __shared__ __align__(128) float smem[];
    __shared__ __align__(8) uint64_t mbar[2];

    const int tid = threadIdx.x;
    const int gy0 = blockIdx.x * NROWS;  // 0,4,..,72
    const int a   = blockIdx.y;          // 0..2
    const int b   = blockIdx.z;          // 0..15

    const float aw = (a == 0) ? 10.0f : (a == 1 ? 16.0f : 33.0f);
    const float ah = (a == 0) ? 13.0f : (a == 1 ? 30.0f : 23.0f);

    float* dst = out + ((size_t)b * (NA * NGG) + a * NGG + (size_t)gy0 * NG) * NCH;

    uint32_t sbase;
    asm("{ .reg .u64 t; cvta.to.shared.u64 t, %1; cvt.u32.u64 %0, t; }"
        : "=r"(sbase) : "l"(smem));
    uint32_t mbase;
    asm("{ .reg .u64 t; cvta.to.shared.u64 t, %1; cvt.u32.u64 %0, t; }"
        : "=r"(mbase) : "l"(mbar));

    const int c1 = a * NCH;   // tensor dim1 coord (channel base)
    // ---- init mbarriers; arm + issue tensor loads for rows 0,1 ----
    if (tid == 0) {
        asm volatile("mbarrier.init.shared.b64 [%0], 1;" :: "r"(mbase)     : "memory");
        asm volatile("mbarrier.init.shared.b64 [%0], 1;" :: "r"(mbase + 8) : "memory");
        asm volatile("fence.proxy.async.shared::cta;" ::: "memory");
        #pragma unroll
        for (int rb = 0; rb < 2; ++rb) {
            asm volatile("mbarrier.arrive.expect_tx.shared.b64 _, [%0], %1;"
                         :: "r"(mbase + rb * 8), "r"((uint32_t)ROW_B) : "memory");
            asm volatile(
                "cp.async.bulk.tensor.3d.shared::cta.global.tile.mbarrier::complete_tx::bytes "
                "[%0], [%1, {%2, %3, %4}], [%5];"
                :: "r"(sbase + (uint32_t)(IN_OFF(rb) * 4)),
                   "l"(&tmap),
                   "r"((gy0 + rb) * NG), "r"(c1), "r"(b),
                   "r"(mbase + rb * 8)
                : "memory");
        }
    }
    __syncthreads();

    // ---- pipeline over rows ----
    #pragma unroll 1
    for (int r = 0; r < NROWS; ++r) {
        const int buf = r & 1;
        const uint32_t mb = mbase + buf * 8;
        const uint32_t ph = (uint32_t)(r >> 1) & 1u;

        // wait input row ready
        {
            uint32_t done;
            asm volatile(
                "{ .reg .pred p; mbarrier.try_wait.parity.shared.b64 p, [%1], %2; "
                "selp.b32 %0, 1, 0, p; }"
                : "=r"(done) : "r"(mb), "r"(ph) : "memory");
            while (!done) {
                asm volatile(
                    "{ .reg .pred p; mbarrier.try_wait.parity.shared.b64 p, [%1], %2, 0x989680; "
                    "selp.b32 %0, 1, 0, p; }"
                    : "=r"(done) : "r"(mb), "r"(ph) : "memory");
            }
        }

        if (tid == 0 && r >= 2) {
            // out[buf] reuse: engine must have read row r-2's store data
            asm volatile("cp.async.bulk.wait_group.read 1;" ::: "memory");
        }
        __syncthreads();

        // ---- compute: in[buf] (c*76+s) -> out[buf] (s*85+c), conflict-free ----
        {
            const float* __restrict__ ib = smem + IN_OFF(buf);
            float* __restrict__ ob = smem + OUT_OFF(buf);
            const float ybase = fmaf((float)(gy0 + r), 8.0f, 4.0f);

            int cg = tid / NG;
            int s  = tid - cg * NG;
            #pragma unroll 1
            for (int i = tid; i < NITEM; i += NTHR) {
                const float* p = ib + (cg << 2) * NG + s;
                const float v0 = p[0];
                const float v1 = p[NG];
                const float v2 = p[2 * NG];
                const float v3 = p[3 * NG];

                float o0, o1, o2, o3;
                if (cg == 0) {
                    o0 = fmaf(tanh_half(v0), 4.0f, fmaf((float)s, 8.0f, 4.0f));
                    o1 = fmaf(tanh_half(v1), 4.0f, ybase);
                    o2 = __expf(v2) * aw;
                    o3 = __expf(v3) * ah;
                } else {
                    o0 = fmaf(tanh_half(v0), 0.5f, 0.5f);
                    o1 = fmaf(tanh_half(v1), 0.5f, 0.5f);
                    o2 = fmaf(tanh_half(v2), 0.5f, 0.5f);
                    o3 = fmaf(tanh_half(v3), 0.5f, 0.5f);
                }
                float* t = ob + s * NCH + (cg << 2);
                t[0] = o0; t[1] = o1; t[2] = o2; t[3] = o3;

                // i += 512 => cg += 6, s += 56  (512 = 6*76 + 56)
                cg += 6; s += 56;
                if (s >= NG) { s -= NG; ++cg; }
            }
            // tail channel 84
            if (tid < NG) {
                ob[tid * NCH + 84] = fmaf(tanh_half(ib[84 * NG + tid]), 0.5f, 0.5f);
            }
        }
        __syncthreads();  // compute done: in[buf] consumed, out[buf] complete

        if (tid == 0) {
            // refill in[buf] with row r+2 (single tensor-TMA op)
            if (r + 2 < NROWS) {
                asm volatile("mbarrier.arrive.expect_tx.shared.b64 _, [%0], %1;"
                             :: "r"(mb), "r"((uint32_t)ROW_B) : "memory");
                asm volatile(
                    "cp.async.bulk.tensor.3d.shared::cta.global.tile.mbarrier::complete_tx::bytes "
                    "[%0], [%1, {%2, %3, %4}], [%5];"
                    :: "r"(sbase + (uint32_t)(IN_OFF(buf) * 4)),
                       "l"(&tmap),
                       "r"((gy0 + r + 2) * NG), "r"(c1), "r"(b),
                       "r"(mb)
                    : "memory");
            }
            // store out[buf] -> gmem row r (25840B of the padded buffer)
            asm volatile("fence.proxy.async.shared::cta;" ::: "memory");
            asm volatile(
                "cp.async.bulk.global.shared::cta.bulk_group [%0], [%1], %2;"
                :: "l"(dst + (size_t)r * ROW_F),
                   "r"(sbase + (uint32_t)(OUT_OFF(buf) * 4)),
                   "r"((uint32_t)ROW_B)
                : "memory");
            asm volatile("cp.async.bulk.commit_group;" ::: "memory");
        }
    }

    // keep CTA alive until the last stores have read smem
    if (tid == 0) {
        asm volatile("cp.async.bulk.wait_group.read 0;" ::: "memory");
    }
}

typedef CUresult (*EncodeTiledFn)(
    CUtensorMap*, CUtensorMapDataType, cuuint32_t, void*,
    const cuuint64_t*, const cuuint64_t*, const cuuint32_t*, const cuuint32_t*,
    CUtensorMapInterleave, CUtensorMapSwizzle, CUtensorMapL2promotion,
    CUtensorMapFloatOOBfill);

extern "C" void kernel_launch(void* const* d_in, const int* in_sizes, int n_in,
                              void* d_out, int out_size) {
    const float* x = (const float*)d_in[0];
    float* out = (float*)d_out;

    // Resolve cuTensorMapEncodeTiled through cudart (no -lcuda at link time).
    void* fn = nullptr;
    cudaDriverEntryPointQueryResult qres;
    cudaGetDriverEntryPoint("cuTensorMapEncodeTiled", &fn,
                            cudaEnableDefault, &qres);
    EncodeTiledFn encode = (EncodeTiledFn)fn;

    // 3D view of x: dim0 = flattened plane (5776), dim1 = channel (255),
    // dim2 = batch (16). Box = one gy row (76) x 85 channels.
    CUtensorMap tmap;
    {
        cuuint64_t dims[3]    = {(cuuint64_t)NGG, (cuuint64_t)(NA * NCH), 16};
        cuuint64_t strides[2] = {(cuuint64_t)NGG * 4,
                                 (cuuint64_t)NGG * 4 * (NA * NCH)};
        cuuint32_t box[3]     = {(cuuint32_t)NG, (cuuint32_t)NCH, 1};
        cuuint32_t estr[3]    = {1, 1, 1};
        encode(&tmap, CU_TENSOR_MAP_DATA_TYPE_FLOAT32, 3, (void*)x,
               dims, strides, box, estr,
               CU_TENSOR_MAP_INTERLEAVE_NONE, CU_TENSOR_MAP_SWIZZLE_NONE,
               CU_TENSOR_MAP_L2_PROMOTION_L2_128B,
               CU_TENSOR_MAP_FLOAT_OOB_FILL_NONE);
    }

    cudaFuncSetAttribute(detection_layer_kernel,
                         cudaFuncAttributeMaxDynamicSharedMemorySize, SMEM_B);

    dim3 grid(NG / NROWS, NA, 16);
    detection_layer_kernel<<<grid, NTHR, SMEM_B>>>(tmap, out);
}

// round 17
// speedup vs baseline: 1.2455x; 1.0411x over previous
#include <cuda_runtime.h>
#include <cuda.h>
#include <cstdint>

// DetectionLayer: x (16, 255, 76, 76) f32 -> out (16, 17328, 85) f32
// Small-footprint serial pipeline, overlap via 4 CTAs/SM:
//   1 x cp.async.bulk.tensor.3d load (box 76 x 85) -> channel-major smem
//   conflict-free smem transform (sigmoid/exp/affine)
//   1 x cp.async.bulk s2g store (25840B)
// Block = one gy row; 51.7KB smem -> 4 CTAs/SM (occ ~89%).

#define NG     76
#define NGG    (NG * NG)      // 5776
#define NA     3
#define NCH    85
#define ROW_F  (NG * NCH)     // 6460 floats
#define ROW_B  (ROW_F * 4)    // 25840 bytes
#define BUF_F  6464           // padded buffer: 25856 B (mult of 128)
#define NITEM  (21 * NG)      // 1596 quad items
#define NTHR   512

// dynamic smem: in @ 0 (channel-major c*76+s), out @ BUF_F (s*85+c)
#define SMEM_B (2 * BUF_F * 4)   // 51712 bytes

__device__ __forceinline__ float tanh_half(float v) {
    float t;
    asm("tanh.approx.f32 %0, %1;" : "=f"(t) : "f"(v * 0.5f));
    return t;  // tanh(v/2); sigmoid(v) = fmaf(t, 0.5f, 0.5f)
}

__global__ __launch_bounds__(NTHR)
void detection_layer_kernel(const __grid_constant__ CUtensorMap tmap,
                            float* __restrict__ out) {
    extern __shared__ __align__(128) float smem[];
    __shared__ __align__(8) uint64_t mbar;

    const int tid = threadIdx.x;
    const int gy  = blockIdx.x;   // 0..75
    const int a   = blockIdx.y;   // 0..2
    const int b   = blockIdx.z;   // 0..15

    const float aw = (a == 0) ? 10.0f : (a == 1 ? 16.0f : 33.0f);
    const float ah = (a == 0) ? 13.0f : (a == 1 ? 30.0f : 23.0f);

    float* dst = out + ((size_t)b * (NA * NGG) + a * NGG + (size_t)gy * NG) * NCH;

    uint32_t sbase;
    asm("{ .reg .u64 t; cvta.to.shared.u64 t, %1; cvt.u32.u64 %0, t; }"
        : "=r"(sbase) : "l"(smem));
    uint32_t mbase;
    asm("{ .reg .u64 t; cvta.to.shared.u64 t, %1; cvt.u32.u64 %0, t; }"
        : "=r"(mbase) : "l"(&mbar));

    // init mbarrier, arm, and issue the single tensor-TMA load
    if (tid == 0) {
        asm volatile("mbarrier.init.shared.b64 [%0], 1;" :: "r"(mbase) : "memory");
        asm volatile("fence.proxy.async.shared::cta;" ::: "memory");
        asm volatile("mbarrier.arrive.expect_tx.shared.b64 _, [%0], %1;"
                     :: "r"(mbase), "r"((uint32_t)ROW_B) : "memory");
        asm volatile(
            "cp.async.bulk.tensor.3d.shared::cta.global.tile.mbarrier::complete_tx::bytes "
            "[%0], [%1, {%2, %3, %4}], [%5];"
            :: "r"(sbase), "l"(&tmap),
               "r"(gy * NG), "r"(a * NCH), "r"(b),
               "r"(mbase)
            : "memory");
    }
    __syncthreads();

    // wait for the input row
    {
        uint32_t done;
        asm volatile(
            "{ .reg .pred p; mbarrier.try_wait.parity.shared.b64 p, [%1], 0; "
            "selp.b32 %0, 1, 0, p; }"
            : "=r"(done) : "r"(mbase) : "memory");
        while (!done) {
            asm volatile(
                "{ .reg .pred p; mbarrier.try_wait.parity.shared.b64 p, [%1], 0, 0x989680; "
                "selp.b32 %0, 1, 0, p; }"
                : "=r"(done) : "r"(mbase) : "memory");
        }
    }
    __syncthreads();

    // ---- compute: in (c*76+s) -> out (s*85+c), conflict-free ----
    {
        const float* __restrict__ ib = smem;
        float* __restrict__ ob = smem + BUF_F;
        const float ybase = fmaf((float)gy, 8.0f, 4.0f);

        int cg = tid / NG;
        int s  = tid - cg * NG;
        #pragma unroll 1
        for (int i = tid; i < NITEM; i += NTHR) {
            const float* p = ib + (cg << 2) * NG + s;
            const float v0 = p[0];
            const float v1 = p[NG];
            const float v2 = p[2 * NG];
            const float v3 = p[3 * NG];

            float o0, o1, o2, o3;
            if (cg == 0) {
                o0 = fmaf(tanh_half(v0), 4.0f, fmaf((float)s, 8.0f, 4.0f));
                o1 = fmaf(tanh_half(v1), 4.0f, ybase);
                o2 = __expf(v2) * aw;
                o3 = __expf(v3) * ah;
            } else {
                o0 = fmaf(tanh_half(v0), 0.5f, 0.5f);
                o1 = fmaf(tanh_half(v1), 0.5f, 0.5f);
                o2 = fmaf(tanh_half(v2), 0.5f, 0.5f);
                o3 = fmaf(tanh_half(v3), 0.5f, 0.5f);
            }
            float* t = ob + s * NCH + (cg << 2);
            t[0] = o0; t[1] = o1; t[2] = o2; t[3] = o3;

            // i += 512 => cg += 6, s += 56  (512 = 6*76 + 56)
            cg += 6; s += 56;
            if (s >= NG) { s -= NG; ++cg; }
        }
        // tail channel 84
        if (tid < NG) {
            ob[tid * NCH + 84] = fmaf(tanh_half(ib[84 * NG + tid]), 0.5f, 0.5f);
        }
    }
    __syncthreads();

    // ---- single bulk store smem -> gmem (25840 B) ----
    if (tid == 0) {
        asm volatile("fence.proxy.async.shared::cta;" ::: "memory");
        asm volatile(
            "cp.async.bulk.global.shared::cta.bulk_group [%0], [%1], %2;"
            :: "l"(dst), "r"(sbase + (uint32_t)(BUF_F * 4)), "r"((uint32_t)ROW_B)
            : "memory");
        asm volatile("cp.async.bulk.commit_group;" ::: "memory");
        // keep CTA alive until the engine has read the tile
        asm volatile("cp.async.bulk.wait_group.read 0;" ::: "memory");
    }
}

typedef CUresult (*EncodeTiledFn)(
    CUtensorMap*, CUtensorMapDataType, cuuint32_t, void*,
    const cuuint64_t*, const cuuint64_t*, const cuuint32_t*, const cuuint32_t*,
    CUtensorMapInterleave, CUtensorMapSwizzle, CUtensorMapL2promotion,
    CUtensorMapFloatOOBfill);

extern "C" void kernel_launch(void* const* d_in, const int* in_sizes, int n_in,
                              void* d_out, int out_size) {
    const float* x = (const float*)d_in[0];
    float* out = (float*)d_out;

    // Resolve cuTensorMapEncodeTiled through cudart (no -lcuda at link time).
    void* fn = nullptr;
    cudaDriverEntryPointQueryResult qres;
    cudaGetDriverEntryPoint("cuTensorMapEncodeTiled", &fn,
                            cudaEnableDefault, &qres);
    EncodeTiledFn encode = (EncodeTiledFn)fn;

    // 3D view of x: dim0 = flattened plane (5776), dim1 = channel (255),
    // dim2 = batch (16). Box = one gy row (76) x 85 channels.
    CUtensorMap tmap;
    {
        cuuint64_t dims[3]    = {(cuuint64_t)NGG, (cuuint64_t)(NA * NCH), 16};
        cuuint64_t strides[2] = {(cuuint64_t)NGG * 4,
                                 (cuuint64_t)NGG * 4 * (NA * NCH)};
        cuuint32_t box[3]     = {(cuuint32_t)NG, (cuuint32_t)NCH, 1};
        cuuint32_t estr[3]    = {1, 1, 1};
        encode(&tmap, CU_TENSOR_MAP_DATA_TYPE_FLOAT32, 3, (void*)x,
               dims, strides, box, estr,
               CU_TENSOR_MAP_INTERLEAVE_NONE, CU_TENSOR_MAP_SWIZZLE_NONE,
               CU_TENSOR_MAP_L2_PROMOTION_L2_128B,
               CU_TENSOR_MAP_FLOAT_OOB_FILL_NONE);
    }

    cudaFuncSetAttribute(detection_layer_kernel,
                         cudaFuncAttributeMaxDynamicSharedMemorySize, SMEM_B);

    dim3 grid(NG, NA, 16);
    detection_layer_kernel<<<grid, NTHR, SMEM_B>>>(tmap, out);
}